// round 1
// baseline (speedup 1.0000x reference)
#include <cuda_runtime.h>
#include <math.h>

#define BATCH 8
#define NQ    1024
#define NKV   4096
#define DIM   512

// ---------------- scratch (device globals: allocation-free) ----------------
__device__ float g_q[BATCH * NQ * DIM];                    //  16.8 MB
__device__ float g_k[BATCH * NKV * DIM];                   //  67 MB
__device__ float g_v[BATCH * NKV * DIM];                   //  67 MB
__device__ float g_attn[(size_t)BATCH * NQ * NKV];         // 134 MB
__device__ float g_x[BATCH * NQ * DIM];                    //  16.8 MB

// ============================================================================
// GEMM NT: C[M,N] = alpha * A[M,K] @ B[N,K]^T   (A,B,C row-major)
// 64x64 tile, BK=16, 256 threads, 4x4 per thread.
// blockIdx.z = batch; sA/sB/sC are per-batch element strides (0 = shared).
// All dims assumed multiples of 64 (M,N) and 16 (K) — true for this problem.
// ============================================================================
__global__ void __launch_bounds__(256) gemm_nt_kernel(
    const float* __restrict__ A, const float* __restrict__ Bm,
    float* __restrict__ C, int M, int N, int K,
    size_t sA, size_t sB, size_t sC, float alpha)
{
    __shared__ float As[16][68];   // [k][m], pad 68 to tame STS conflicts
    __shared__ float Bs[16][68];   // [k][n]

    A  += (size_t)blockIdx.z * sA;
    Bm += (size_t)blockIdx.z * sB;
    C  += (size_t)blockIdx.z * sC;

    const int m0 = blockIdx.y * 64;
    const int n0 = blockIdx.x * 64;
    const int t  = threadIdx.x;

    // load mapping: each thread fetches one float4 along K and transposes
    const int lm = t >> 2;        // 0..63
    const int kq = t & 3;         // 0..3  -> k = 4*kq..4*kq+3

    // compute mapping
    const int tx = t & 15;        // n group
    const int ty = t >> 4;        // m group

    float acc[4][4] = {};

    for (int k0 = 0; k0 < K; k0 += 16) {
        float4 av = *(const float4*)&A [(size_t)(m0 + lm) * K + k0 + 4 * kq];
        float4 bv = *(const float4*)&Bm[(size_t)(n0 + lm) * K + k0 + 4 * kq];
        As[4*kq + 0][lm] = av.x;  As[4*kq + 1][lm] = av.y;
        As[4*kq + 2][lm] = av.z;  As[4*kq + 3][lm] = av.w;
        Bs[4*kq + 0][lm] = bv.x;  Bs[4*kq + 1][lm] = bv.y;
        Bs[4*kq + 2][lm] = bv.z;  Bs[4*kq + 3][lm] = bv.w;
        __syncthreads();

        #pragma unroll
        for (int kk = 0; kk < 16; kk++) {
            float4 a4 = *(const float4*)&As[kk][ty * 4];
            float4 b4 = *(const float4*)&Bs[kk][tx * 4];
            float a[4] = {a4.x, a4.y, a4.z, a4.w};
            float b[4] = {b4.x, b4.y, b4.z, b4.w};
            #pragma unroll
            for (int i = 0; i < 4; i++)
                #pragma unroll
                for (int j = 0; j < 4; j++)
                    acc[i][j] += a[i] * b[j];
        }
        __syncthreads();
    }

    #pragma unroll
    for (int i = 0; i < 4; i++) {
        float4 o = make_float4(acc[i][0] * alpha, acc[i][1] * alpha,
                               acc[i][2] * alpha, acc[i][3] * alpha);
        *(float4*)&C[(size_t)(m0 + ty * 4 + i) * N + n0 + tx * 4] = o;
    }
}

// ============================================================================
// GEMM NN: C[M,N] = A[M,K] @ B[K,N]   (all row-major)
// ============================================================================
__global__ void __launch_bounds__(256) gemm_nn_kernel(
    const float* __restrict__ A, const float* __restrict__ Bm,
    float* __restrict__ C, int M, int N, int K,
    size_t sA, size_t sB, size_t sC)
{
    __shared__ float As[16][68];   // [k][m]
    __shared__ float Bs[16][68];   // [k][n]

    A  += (size_t)blockIdx.z * sA;
    Bm += (size_t)blockIdx.z * sB;
    C  += (size_t)blockIdx.z * sC;

    const int m0 = blockIdx.y * 64;
    const int n0 = blockIdx.x * 64;
    const int t  = threadIdx.x;

    const int lm = t >> 2;        // 0..63 (A load)
    const int kq = t & 3;         // 0..3

    const int bk  = t >> 4;       // 0..15 (B load: k row)
    const int bn4 = t & 15;       // float4 index along n

    const int tx = t & 15;
    const int ty = t >> 4;

    float acc[4][4] = {};

    for (int k0 = 0; k0 < K; k0 += 16) {
        float4 av = *(const float4*)&A[(size_t)(m0 + lm) * K + k0 + 4 * kq];
        As[4*kq + 0][lm] = av.x;  As[4*kq + 1][lm] = av.y;
        As[4*kq + 2][lm] = av.z;  As[4*kq + 3][lm] = av.w;

        float4 bv = *(const float4*)&Bm[(size_t)(k0 + bk) * N + n0 + 4 * bn4];
        *(float4*)&Bs[bk][4 * bn4] = bv;
        __syncthreads();

        #pragma unroll
        for (int kk = 0; kk < 16; kk++) {
            float4 a4 = *(const float4*)&As[kk][ty * 4];
            float4 b4 = *(const float4*)&Bs[kk][tx * 4];
            float a[4] = {a4.x, a4.y, a4.z, a4.w};
            float b[4] = {b4.x, b4.y, b4.z, b4.w};
            #pragma unroll
            for (int i = 0; i < 4; i++)
                #pragma unroll
                for (int j = 0; j < 4; j++)
                    acc[i][j] += a[i] * b[j];
        }
        __syncthreads();
    }

    #pragma unroll
    for (int i = 0; i < 4; i++) {
        float4 o = make_float4(acc[i][0], acc[i][1], acc[i][2], acc[i][3]);
        *(float4*)&C[(size_t)(m0 + ty * 4 + i) * N + n0 + tx * 4] = o;
    }
}

// ============================================================================
// Masked softmax over rows of attn [BATCH*NQ, NKV]; mask int32 [BATCH, NKV],
// nonzero = keep. bias = -10000 for masked (matches reference exactly).
// One block of 256 threads per row; row cached in registers (16 per thread).
// ============================================================================
__global__ void __launch_bounds__(256) softmax_kernel(
    float* __restrict__ attn, const int* __restrict__ mask)
{
    const int row = blockIdx.x;            // b*NQ + n
    const int b   = row >> 10;             // NQ = 1024
    float* p = attn + (size_t)row * NKV;
    const int* mrow = mask + b * NKV;

    float v[16];
    float mx = -3.0e38f;
    #pragma unroll
    for (int i = 0; i < 16; i++) {
        int m = threadIdx.x + i * 256;
        float x = p[m] + (mrow[m] ? 0.0f : -10000.0f);
        v[i] = x;
        mx = fmaxf(mx, x);
    }

    __shared__ float red[8];
    #pragma unroll
    for (int o = 16; o; o >>= 1) mx = fmaxf(mx, __shfl_xor_sync(0xffffffffu, mx, o));
    if ((threadIdx.x & 31) == 0) red[threadIdx.x >> 5] = mx;
    __syncthreads();
    float bm = red[0];
    #pragma unroll
    for (int w = 1; w < 8; w++) bm = fmaxf(bm, red[w]);
    __syncthreads();

    float sum = 0.0f;
    #pragma unroll
    for (int i = 0; i < 16; i++) {
        v[i] = __expf(v[i] - bm);
        sum += v[i];
    }
    #pragma unroll
    for (int o = 16; o; o >>= 1) sum += __shfl_xor_sync(0xffffffffu, sum, o);
    if ((threadIdx.x & 31) == 0) red[threadIdx.x >> 5] = sum;
    __syncthreads();
    float ts = red[0];
    #pragma unroll
    for (int w = 1; w < 8; w++) ts += red[w];
    float inv = 1.0f / ts;

    #pragma unroll
    for (int i = 0; i < 16; i++) {
        int m = threadIdx.x + i * 256;
        p[m] = v[i] * inv;
    }
}

// ============================================================================
// launch
// ============================================================================
extern "C" void kernel_launch(void* const* d_in, const int* in_sizes, int n_in,
                              void* d_out, int out_size)
{
    const float* prototype = (const float*)d_in[0];   // [B, NQ, DIM]
    const float* q_x       = (const float*)d_in[1];   // [B, NKV, DIM]
    const int*   mask      = (const int*)  d_in[2];   // [B, NKV] (bool->int32)
    const float* Wq        = (const float*)d_in[3];   // [DIM, DIM]
    const float* Wk        = (const float*)d_in[4];
    const float* Wv        = (const float*)d_in[5];
    const float* Wproj     = (const float*)d_in[6];
    float* out = (float*)d_out;                        // [B, NQ, DIM] fp32

    float *qb, *kb, *vb, *attn, *xb;
    cudaGetSymbolAddress((void**)&qb,   g_q);
    cudaGetSymbolAddress((void**)&kb,   g_k);
    cudaGetSymbolAddress((void**)&vb,   g_v);
    cudaGetSymbolAddress((void**)&attn, g_attn);
    cudaGetSymbolAddress((void**)&xb,   g_x);

    const float scale = 0.04419417382415922f;  // DIM^-0.5 = 1/sqrt(512)
    dim3 blk(256);

    // q = prototype @ Wq^T   : M = B*NQ = 8192, N = K = 512
    gemm_nt_kernel<<<dim3(DIM / 64, (BATCH * NQ) / 64), blk>>>(
        prototype, Wq, qb, BATCH * NQ, DIM, DIM, 0, 0, 0, 1.0f);

    // k = q_x @ Wk^T, v = q_x @ Wv^T : M = B*NKV = 32768
    gemm_nt_kernel<<<dim3(DIM / 64, (BATCH * NKV) / 64), blk>>>(
        q_x, Wk, kb, BATCH * NKV, DIM, DIM, 0, 0, 0, 1.0f);
    gemm_nt_kernel<<<dim3(DIM / 64, (BATCH * NKV) / 64), blk>>>(
        q_x, Wv, vb, BATCH * NKV, DIM, DIM, 0, 0, 0, 1.0f);

    // attn = scale * q @ k^T per batch : [1024, 4096], K = 512
    gemm_nt_kernel<<<dim3(NKV / 64, NQ / 64, BATCH), blk>>>(
        qb, kb, attn, NQ, NKV, DIM,
        (size_t)NQ * DIM, (size_t)NKV * DIM, (size_t)NQ * NKV, scale);

    // masked softmax over last axis
    softmax_kernel<<<BATCH * NQ, blk>>>(attn, mask);

    // x = attn @ v per batch : [1024, 512], K = 4096
    gemm_nn_kernel<<<dim3(DIM / 64, NQ / 64, BATCH), blk>>>(
        attn, vb, xb, NQ, DIM, NKV,
        (size_t)NQ * NKV, (size_t)NKV * DIM, (size_t)NQ * DIM);

    // out = x @ Wproj^T : M = B*NQ = 8192
    gemm_nt_kernel<<<dim3(DIM / 64, (BATCH * NQ) / 64), blk>>>(
        xb, Wproj, out, BATCH * NQ, DIM, DIM, 0, 0, 0, 1.0f);
}

// round 4
// speedup vs baseline: 1.5788x; 1.5788x over previous
#include <cuda_runtime.h>
#include <cstdint>
#include <math.h>

#define BATCH 8
#define NQ    1024
#define NKV   4096
#define DIM   512

// ---------------- scratch (device globals: allocation-free) ----------------
__device__ float g_q[BATCH * NQ * DIM];                    //  16.8 MB
__device__ float g_k[BATCH * NKV * DIM];                   //  67 MB
__device__ float g_vT[BATCH * DIM * NKV];                  //  67 MB (v transposed per batch)
__device__ float g_attn[(size_t)BATCH * NQ * NKV];         // 134 MB
__device__ float g_x[BATCH * NQ * DIM];                    //  16.8 MB

// ============================================================================
// helpers
// ============================================================================
__device__ __forceinline__ uint32_t smem_u32(const void* p) {
    uint32_t a;
    asm("{ .reg .u64 t; cvta.to.shared.u64 t, %1; cvt.u32.u64 %0, t; }"
        : "=r"(a) : "l"(p));
    return a;
}

__device__ __forceinline__ void cp_async16(uint32_t saddr, const void* gaddr) {
    asm volatile("cp.async.ca.shared.global [%0], [%1], 16;"
                 :: "r"(saddr), "l"(gaddr) : "memory");
}
__device__ __forceinline__ void cp_commit() {
    asm volatile("cp.async.commit_group;" ::: "memory");
}
__device__ __forceinline__ void cp_wait1() {
    asm volatile("cp.async.wait_group 1;" ::: "memory");
}
__device__ __forceinline__ void cp_wait0() {
    asm volatile("cp.async.wait_group 0;" ::: "memory");
}

// mma.sync m16n8k8 tf32: d += a*b (f32 accumulators in-place)
__device__ __forceinline__ void mma_tf32(float* d, const uint32_t* a, const uint32_t* b) {
    asm volatile(
        "mma.sync.aligned.m16n8k8.row.col.f32.tf32.tf32.f32 "
        "{%0,%1,%2,%3}, {%4,%5,%6,%7}, {%8,%9}, {%0,%1,%2,%3};"
        : "+f"(d[0]), "+f"(d[1]), "+f"(d[2]), "+f"(d[3])
        : "r"(a[0]), "r"(a[1]), "r"(a[2]), "r"(a[3]), "r"(b[0]), "r"(b[1]));
}

// 3xTF32 split: x -> hi (RNE tf32) + lo (RNE tf32 of residual)
__device__ __forceinline__ void tf32_split(float x, uint32_t& hi, uint32_t& lo) {
    asm("cvt.rna.tf32.f32 %0, %1;" : "=r"(hi) : "f"(x));
    float r = x - __uint_as_float(hi);
    asm("cvt.rna.tf32.f32 %0, %1;" : "=r"(lo) : "f"(r));
}

// ============================================================================
// 3xTF32 mma.sync GEMM NT: C[M,N] = alpha * A[M,K] @ B[N,K]^T  (row-major fp32)
// CTA tile 128x128, K-tile 32, 2-stage cp.async, 256 threads (8 warps, 2x4).
// Warp tile 64x32. SMEM rows padded to 44 floats -> conflict-free frag LDS.
// Each product computed as a_lo*b_hi + a_hi*b_lo + a_hi*b_hi (fp32-like acc).
// blockIdx.z = batch; sA/sB/sC per-batch element strides (0 = broadcast).
// Requires M,N % 128 == 0, K % 32 == 0 (true for all calls here).
// ============================================================================
#define PAD   44
#define TSZ   (128 * PAD)          // floats per matrix tile
#define STAGE (2 * TSZ)            // floats per stage (A + B)
#define GEMM_SMEM (2 * STAGE * 4)  // bytes, 2 stages = 90112

__global__ void __launch_bounds__(256, 2) gemm_nt_mma(
    const float* __restrict__ A, const float* __restrict__ B,
    float* __restrict__ C, int M, int N, int K,
    size_t sA, size_t sB, size_t sC, float alpha)
{
    extern __shared__ float smem[];
    const uint32_t sbase = smem_u32(smem);

    const int t    = threadIdx.x;
    const int wid  = t >> 5;
    const int lane = t & 31;
    const int g    = lane >> 2;     // group row 0..7
    const int c    = lane & 3;      // 0..3
    const int warp_m = wid >> 2;    // 0..1
    const int warp_n = wid & 3;     // 0..3

    A += (size_t)blockIdx.z * sA;
    B += (size_t)blockIdx.z * sB;
    C += (size_t)blockIdx.z * sC;
    const int m0 = blockIdx.y * 128;
    const int n0 = blockIdx.x * 128;

    // ---- async load of one K-tile (32 floats wide) into stage s ----
    auto load_tile = [&](int kt, int s) {
        const uint32_t as = sbase + (uint32_t)(s * STAGE) * 4u;
        const uint32_t bs = as + (uint32_t)TSZ * 4u;
        const int kbase = kt * 32;
        #pragma unroll
        for (int p = 0; p < 4; p++) {
            int idx = p * 256 + t;          // 0..1023
            int row = idx >> 3;             // 0..127
            int c4  = idx & 7;              // float4 slot in the 32-wide slice
            uint32_t soff = (uint32_t)(row * PAD + c4 * 4) * 4u;
            cp_async16(as + soff, A + (size_t)(m0 + row) * K + kbase + c4 * 4);
            cp_async16(bs + soff, B + (size_t)(n0 + row) * K + kbase + c4 * 4);
        }
        cp_commit();
    };

    float acc[4][4][4] = {};   // [mtile][ntile][reg]

    const int nkt = K >> 5;
    load_tile(0, 0);

    for (int kt = 0; kt < nkt; kt++) {
        const int s = kt & 1;
        if (kt + 1 < nkt) {
            load_tile(kt + 1, s ^ 1);
            cp_wait1();
        } else {
            cp_wait0();
        }
        __syncthreads();

        const float* As = smem + s * STAGE + warp_m * 64 * PAD;
        const float* Bs = smem + s * STAGE + TSZ + warp_n * 32 * PAD;

        #pragma unroll
        for (int ks = 0; ks < 4; ks++) {
            const int kc = ks * 8 + c;
            uint32_t ah[4][4], al[4][4];
            #pragma unroll
            for (int mt = 0; mt < 4; mt++) {
                const int r0 = mt * 16 + g;
                tf32_split(As[r0 * PAD + kc],           ah[mt][0], al[mt][0]);
                tf32_split(As[(r0 + 8) * PAD + kc],     ah[mt][1], al[mt][1]);
                tf32_split(As[r0 * PAD + kc + 4],       ah[mt][2], al[mt][2]);
                tf32_split(As[(r0 + 8) * PAD + kc + 4], ah[mt][3], al[mt][3]);
            }
            uint32_t bh[4][2], bl[4][2];
            #pragma unroll
            for (int nt = 0; nt < 4; nt++) {
                const int r0 = nt * 8 + g;
                tf32_split(Bs[r0 * PAD + kc],     bh[nt][0], bl[nt][0]);
                tf32_split(Bs[r0 * PAD + kc + 4], bh[nt][1], bl[nt][1]);
            }
            #pragma unroll
            for (int mt = 0; mt < 4; mt++)
                #pragma unroll
                for (int nt = 0; nt < 4; nt++) {
                    mma_tf32(acc[mt][nt], al[mt], bh[nt]);  // small terms first
                    mma_tf32(acc[mt][nt], ah[mt], bl[nt]);
                    mma_tf32(acc[mt][nt], ah[mt], bh[nt]);
                }
        }
        __syncthreads();
    }

    // ---- epilogue: c0,c1 at (row, 2c..2c+1), c2,c3 at (row+8, same cols) ----
    #pragma unroll
    for (int mt = 0; mt < 4; mt++) {
        const int row = m0 + warp_m * 64 + mt * 16 + g;
        #pragma unroll
        for (int nt = 0; nt < 4; nt++) {
            const int col = n0 + warp_n * 32 + nt * 8 + 2 * c;
            float2* p0 = (float2*)(C + (size_t)row * N + col);
            float2* p1 = (float2*)(C + (size_t)(row + 8) * N + col);
            *p0 = make_float2(acc[mt][nt][0] * alpha, acc[mt][nt][1] * alpha);
            *p1 = make_float2(acc[mt][nt][2] * alpha, acc[mt][nt][3] * alpha);
        }
    }
}

// ============================================================================
// Masked softmax over rows of attn [BATCH*NQ, NKV]; mask int32 [B, NKV].
// ============================================================================
__global__ void __launch_bounds__(256) softmax_kernel(
    float* __restrict__ attn, const int* __restrict__ mask)
{
    const int row = blockIdx.x;
    const int b   = row >> 10;             // NQ = 1024
    float* p = attn + (size_t)row * NKV;
    const int* mrow = mask + b * NKV;

    float v[16];
    float mx = -3.0e38f;
    #pragma unroll
    for (int i = 0; i < 16; i++) {
        int m = threadIdx.x + i * 256;
        float x = p[m] + (mrow[m] ? 0.0f : -10000.0f);
        v[i] = x;
        mx = fmaxf(mx, x);
    }

    __shared__ float red[8];
    #pragma unroll
    for (int o = 16; o; o >>= 1) mx = fmaxf(mx, __shfl_xor_sync(0xffffffffu, mx, o));
    if ((threadIdx.x & 31) == 0) red[threadIdx.x >> 5] = mx;
    __syncthreads();
    float bm = red[0];
    #pragma unroll
    for (int w = 1; w < 8; w++) bm = fmaxf(bm, red[w]);
    __syncthreads();

    float sum = 0.0f;
    #pragma unroll
    for (int i = 0; i < 16; i++) {
        v[i] = __expf(v[i] - bm);
        sum += v[i];
    }
    #pragma unroll
    for (int o = 16; o; o >>= 1) sum += __shfl_xor_sync(0xffffffffu, sum, o);
    if ((threadIdx.x & 31) == 0) red[threadIdx.x >> 5] = sum;
    __syncthreads();
    float ts = red[0];
    #pragma unroll
    for (int w = 1; w < 8; w++) ts += red[w];
    float inv = 1.0f / ts;

    #pragma unroll
    for (int i = 0; i < 16; i++) {
        int m = threadIdx.x + i * 256;
        p[m] = v[i] * inv;
    }
}

// ============================================================================
// launch
// ============================================================================
extern "C" void kernel_launch(void* const* d_in, const int* in_sizes, int n_in,
                              void* d_out, int out_size)
{
    const float* prototype = (const float*)d_in[0];   // [B, NQ, DIM]
    const float* q_x       = (const float*)d_in[1];   // [B, NKV, DIM]
    const int*   mask      = (const int*)  d_in[2];   // [B, NKV] (bool->int32)
    const float* Wq        = (const float*)d_in[3];   // [DIM, DIM]
    const float* Wk        = (const float*)d_in[4];
    const float* Wv        = (const float*)d_in[5];
    const float* Wproj     = (const float*)d_in[6];
    float* out = (float*)d_out;                        // [B, NQ, DIM] fp32

    float *qb, *kb, *vtb, *attn, *xb;
    cudaGetSymbolAddress((void**)&qb,   g_q);
    cudaGetSymbolAddress((void**)&kb,   g_k);
    cudaGetSymbolAddress((void**)&vtb,  g_vT);
    cudaGetSymbolAddress((void**)&attn, g_attn);
    cudaGetSymbolAddress((void**)&xb,   g_x);

    cudaFuncSetAttribute(gemm_nt_mma,
                         cudaFuncAttributeMaxDynamicSharedMemorySize, GEMM_SMEM);

    const float scale = 0.04419417382415922f;  // 1/sqrt(512)
    dim3 blk(256);

    // q = prototype @ Wq^T : M=8192, N=512, K=512
    gemm_nt_mma<<<dim3(DIM/128, (BATCH*NQ)/128, 1), blk, GEMM_SMEM>>>(
        prototype, Wq, qb, BATCH*NQ, DIM, DIM, 0, 0, 0, 1.0f);

    // k = q_x @ Wk^T : M=32768, N=512, K=512
    gemm_nt_mma<<<dim3(DIM/128, (BATCH*NKV)/128, 1), blk, GEMM_SMEM>>>(
        q_x, Wk, kb, BATCH*NKV, DIM, DIM, 0, 0, 0, 1.0f);

    // vT[b] = Wv @ q_x[b]^T : per batch M=512, N=4096, K=512
    gemm_nt_mma<<<dim3(NKV/128, DIM/128, BATCH), blk, GEMM_SMEM>>>(
        Wv, q_x, vtb, DIM, NKV, DIM,
        0, (size_t)NKV*DIM, (size_t)DIM*NKV, 1.0f);

    // attn[b] = scale * q[b] @ k[b]^T : M=1024, N=4096, K=512
    gemm_nt_mma<<<dim3(NKV/128, NQ/128, BATCH), blk, GEMM_SMEM>>>(
        qb, kb, attn, NQ, NKV, DIM,
        (size_t)NQ*DIM, (size_t)NKV*DIM, (size_t)NQ*NKV, scale);

    // masked softmax over last axis
    softmax_kernel<<<BATCH*NQ, 256>>>(attn, mask);

    // x[b] = attn[b] @ vT[b]^T : M=1024, N=512, K=4096  (NT, both K-major)
    gemm_nt_mma<<<dim3(DIM/128, NQ/128, BATCH), blk, GEMM_SMEM>>>(
        attn, vtb, xb, NQ, DIM, NKV,
        (size_t)NQ*NKV, (size_t)DIM*NKV, (size_t)NQ*DIM, 1.0f);

    // out = x @ Wproj^T : M=8192, N=512, K=512
    gemm_nt_mma<<<dim3(DIM/128, (BATCH*NQ)/128, 1), blk, GEMM_SMEM>>>(
        xb, Wproj, out, BATCH*NQ, DIM, DIM, 0, 0, 0, 1.0f);
}

// round 5
// speedup vs baseline: 2.6400x; 1.6722x over previous
#include <cuda_runtime.h>
#include <cstdint>
#include <math.h>

#define BATCH 8
#define NQ    1024
#define NKV   4096
#define DIM   512

// ---------------- scratch (device globals: allocation-free) ----------------
__device__ float g_q[BATCH * NQ * DIM];                    //  16.8 MB
__device__ float g_k[BATCH * NKV * DIM];                   //  67 MB
__device__ float g_vT[BATCH * DIM * NKV];                  //  67 MB (v transposed per batch)
__device__ float g_attn[(size_t)BATCH * NQ * NKV];         // 134 MB
__device__ float g_x[BATCH * NQ * DIM];                    //  16.8 MB

// ============================================================================
// helpers
// ============================================================================
__device__ __forceinline__ uint32_t smem_u32(const void* p) {
    uint32_t a;
    asm("{ .reg .u64 t; cvta.to.shared.u64 t, %1; cvt.u32.u64 %0, t; }"
        : "=r"(a) : "l"(p));
    return a;
}

__device__ __forceinline__ void cp_async16(uint32_t saddr, const void* gaddr) {
    asm volatile("cp.async.ca.shared.global [%0], [%1], 16;"
                 :: "r"(saddr), "l"(gaddr) : "memory");
}
__device__ __forceinline__ void cp_commit() {
    asm volatile("cp.async.commit_group;" ::: "memory");
}
__device__ __forceinline__ void cp_wait1() {
    asm volatile("cp.async.wait_group 1;" ::: "memory");
}
__device__ __forceinline__ void cp_wait0() {
    asm volatile("cp.async.wait_group 0;" ::: "memory");
}

// mma.sync m16n8k16 bf16: d += a*b (f32 accumulators in-place)
__device__ __forceinline__ void mma_bf16(float* d, const uint32_t* a, const uint32_t* b) {
    asm volatile(
        "mma.sync.aligned.m16n8k16.row.col.f32.bf16.bf16.f32 "
        "{%0,%1,%2,%3}, {%4,%5,%6,%7}, {%8,%9}, {%0,%1,%2,%3};"
        : "+f"(d[0]), "+f"(d[1]), "+f"(d[2]), "+f"(d[3])
        : "r"(a[0]), "r"(a[1]), "r"(a[2]), "r"(a[3]), "r"(b[0]), "r"(b[1]));
}

// bf16x3 split of a k-adjacent float2: hi = RNE bf16x2 of (x,y),
// lo = RNE bf16x2 of residuals. Packed {k_even -> low 16, k_odd -> high 16}.
__device__ __forceinline__ void bf16x3_split(float2 v, uint32_t& hi, uint32_t& lo) {
    asm("cvt.rn.bf16x2.f32 %0, %1, %2;" : "=r"(hi) : "f"(v.y), "f"(v.x));
    float h0 = __uint_as_float(hi << 16);          // exact bf16 -> f32
    float h1 = __uint_as_float(hi & 0xFFFF0000u);
    float r0 = v.x - h0;
    float r1 = v.y - h1;
    asm("cvt.rn.bf16x2.f32 %0, %1, %2;" : "=r"(lo) : "f"(r1), "f"(r0));
}

// ============================================================================
// bf16x3 mma.sync GEMM NT: C[M,N] = alpha * A[M,K] @ B[N,K]^T  (row-major fp32)
// CTA tile 128x128, K-tile 32 (2 x k16 steps), 2-stage cp.async, 256 threads
// (8 warps, 2x4; warp tile 64x32). SMEM rows padded to 40 floats:
// PAD%32==8 makes the LDS.64 fragment loads hit all 32 banks conflict-free.
// Each product: a_lo*b_hi + a_hi*b_lo + a_hi*b_hi  (~2^-17 per-product error).
// blockIdx.z = batch; sA/sB/sC per-batch element strides (0 = broadcast).
// Requires M,N % 128 == 0, K % 32 == 0 (true for all calls here).
// ============================================================================
#define PAD   40
#define TSZ   (128 * PAD)          // floats per matrix tile (5120)
#define STAGE (2 * TSZ)            // floats per stage (A + B)
#define GEMM_SMEM (2 * STAGE * 4)  // bytes, 2 stages = 81920

__global__ void __launch_bounds__(256, 2) gemm_nt_mma(
    const float* __restrict__ A, const float* __restrict__ B,
    float* __restrict__ C, int M, int N, int K,
    size_t sA, size_t sB, size_t sC, float alpha)
{
    extern __shared__ float smem[];
    const uint32_t sbase = smem_u32(smem);

    const int t    = threadIdx.x;
    const int wid  = t >> 5;
    const int lane = t & 31;
    const int g    = lane >> 2;     // group row 0..7
    const int c    = lane & 3;      // 0..3
    const int warp_m = wid >> 2;    // 0..1
    const int warp_n = wid & 3;     // 0..3

    A += (size_t)blockIdx.z * sA;
    B += (size_t)blockIdx.z * sB;
    C += (size_t)blockIdx.z * sC;
    const int m0 = blockIdx.y * 128;
    const int n0 = blockIdx.x * 128;

    // ---- async load of one K-tile (32 floats wide) into stage s ----
    auto load_tile = [&](int kt, int s) {
        const uint32_t as = sbase + (uint32_t)(s * STAGE) * 4u;
        const uint32_t bs = as + (uint32_t)TSZ * 4u;
        const int kbase = kt * 32;
        #pragma unroll
        for (int p = 0; p < 4; p++) {
            int idx = p * 256 + t;          // 0..1023
            int row = idx >> 3;             // 0..127
            int c4  = idx & 7;              // float4 slot in the 32-wide slice
            uint32_t soff = (uint32_t)(row * PAD + c4 * 4) * 4u;
            cp_async16(as + soff, A + (size_t)(m0 + row) * K + kbase + c4 * 4);
            cp_async16(bs + soff, B + (size_t)(n0 + row) * K + kbase + c4 * 4);
        }
        cp_commit();
    };

    float acc[4][4][4] = {};   // [mtile][ntile][reg]

    const int nkt = K >> 5;
    load_tile(0, 0);

    for (int kt = 0; kt < nkt; kt++) {
        const int s = kt & 1;
        if (kt + 1 < nkt) {
            load_tile(kt + 1, s ^ 1);
            cp_wait1();
        } else {
            cp_wait0();
        }
        __syncthreads();

        const float* As = smem + s * STAGE + warp_m * 64 * PAD;
        const float* Bs = smem + s * STAGE + TSZ + warp_n * 32 * PAD;

        #pragma unroll
        for (int ks2 = 0; ks2 < 2; ks2++) {
            const int kc = ks2 * 16 + 2 * c;      // k-pair base column

            // B fragments for all 4 n-tiles (shared across mt loop)
            uint32_t bh[4][2], bl[4][2];
            #pragma unroll
            for (int nt = 0; nt < 4; nt++) {
                const int r0 = nt * 8 + g;
                bf16x3_split(*(const float2*)&Bs[r0 * PAD + kc],     bh[nt][0], bl[nt][0]);
                bf16x3_split(*(const float2*)&Bs[r0 * PAD + kc + 8], bh[nt][1], bl[nt][1]);
            }

            #pragma unroll
            for (int mt = 0; mt < 4; mt++) {
                const int r0 = mt * 16 + g;
                uint32_t ah[4], al[4];
                bf16x3_split(*(const float2*)&As[r0 * PAD + kc],           ah[0], al[0]);
                bf16x3_split(*(const float2*)&As[(r0 + 8) * PAD + kc],     ah[1], al[1]);
                bf16x3_split(*(const float2*)&As[r0 * PAD + kc + 8],       ah[2], al[2]);
                bf16x3_split(*(const float2*)&As[(r0 + 8) * PAD + kc + 8], ah[3], al[3]);
                #pragma unroll
                for (int nt = 0; nt < 4; nt++) {
                    mma_bf16(acc[mt][nt], al, bh[nt]);   // small terms first
                    mma_bf16(acc[mt][nt], ah, bl[nt]);
                    mma_bf16(acc[mt][nt], ah, bh[nt]);
                }
            }
        }
        __syncthreads();
    }

    // ---- epilogue: c0,c1 at (row, 2c..2c+1), c2,c3 at (row+8, same cols) ----
    #pragma unroll
    for (int mt = 0; mt < 4; mt++) {
        const int row = m0 + warp_m * 64 + mt * 16 + g;
        #pragma unroll
        for (int nt = 0; nt < 4; nt++) {
            const int col = n0 + warp_n * 32 + nt * 8 + 2 * c;
            float2* p0 = (float2*)(C + (size_t)row * N + col);
            float2* p1 = (float2*)(C + (size_t)(row + 8) * N + col);
            *p0 = make_float2(acc[mt][nt][0] * alpha, acc[mt][nt][1] * alpha);
            *p1 = make_float2(acc[mt][nt][2] * alpha, acc[mt][nt][3] * alpha);
        }
    }
}

// ============================================================================
// Masked softmax over rows of attn [BATCH*NQ, NKV]; mask int32 [B, NKV].
// ============================================================================
__global__ void __launch_bounds__(256) softmax_kernel(
    float* __restrict__ attn, const int* __restrict__ mask)
{
    const int row = blockIdx.x;
    const int b   = row >> 10;             // NQ = 1024
    float* p = attn + (size_t)row * NKV;
    const int* mrow = mask + b * NKV;

    float v[16];
    float mx = -3.0e38f;
    #pragma unroll
    for (int i = 0; i < 16; i++) {
        int m = threadIdx.x + i * 256;
        float x = p[m] + (mrow[m] ? 0.0f : -10000.0f);
        v[i] = x;
        mx = fmaxf(mx, x);
    }

    __shared__ float red[8];
    #pragma unroll
    for (int o = 16; o; o >>= 1) mx = fmaxf(mx, __shfl_xor_sync(0xffffffffu, mx, o));
    if ((threadIdx.x & 31) == 0) red[threadIdx.x >> 5] = mx;
    __syncthreads();
    float bm = red[0];
    #pragma unroll
    for (int w = 1; w < 8; w++) bm = fmaxf(bm, red[w]);
    __syncthreads();

    float sum = 0.0f;
    #pragma unroll
    for (int i = 0; i < 16; i++) {
        v[i] = __expf(v[i] - bm);
        sum += v[i];
    }
    #pragma unroll
    for (int o = 16; o; o >>= 1) sum += __shfl_xor_sync(0xffffffffu, sum, o);
    if ((threadIdx.x & 31) == 0) red[threadIdx.x >> 5] = sum;
    __syncthreads();
    float ts = red[0];
    #pragma unroll
    for (int w = 1; w < 8; w++) ts += red[w];
    float inv = 1.0f / ts;

    #pragma unroll
    for (int i = 0; i < 16; i++) {
        int m = threadIdx.x + i * 256;
        p[m] = v[i] * inv;
    }
}

// ============================================================================
// launch
// ============================================================================
extern "C" void kernel_launch(void* const* d_in, const int* in_sizes, int n_in,
                              void* d_out, int out_size)
{
    const float* prototype = (const float*)d_in[0];   // [B, NQ, DIM]
    const float* q_x       = (const float*)d_in[1];   // [B, NKV, DIM]
    const int*   mask      = (const int*)  d_in[2];   // [B, NKV] (bool->int32)
    const float* Wq        = (const float*)d_in[3];   // [DIM, DIM]
    const float* Wk        = (const float*)d_in[4];
    const float* Wv        = (const float*)d_in[5];
    const float* Wproj     = (const float*)d_in[6];
    float* out = (float*)d_out;                        // [B, NQ, DIM] fp32

    float *qb, *kb, *vtb, *attn, *xb;
    cudaGetSymbolAddress((void**)&qb,   g_q);
    cudaGetSymbolAddress((void**)&kb,   g_k);
    cudaGetSymbolAddress((void**)&vtb,  g_vT);
    cudaGetSymbolAddress((void**)&attn, g_attn);
    cudaGetSymbolAddress((void**)&xb,   g_x);

    cudaFuncSetAttribute(gemm_nt_mma,
                         cudaFuncAttributeMaxDynamicSharedMemorySize, GEMM_SMEM);

    const float scale = 0.04419417382415922f;  // 1/sqrt(512)
    dim3 blk(256);

    // q = prototype @ Wq^T : M=8192, N=512, K=512
    gemm_nt_mma<<<dim3(DIM/128, (BATCH*NQ)/128, 1), blk, GEMM_SMEM>>>(
        prototype, Wq, qb, BATCH*NQ, DIM, DIM, 0, 0, 0, 1.0f);

    // k = q_x @ Wk^T : M=32768, N=512, K=512
    gemm_nt_mma<<<dim3(DIM/128, (BATCH*NKV)/128, 1), blk, GEMM_SMEM>>>(
        q_x, Wk, kb, BATCH*NKV, DIM, DIM, 0, 0, 0, 1.0f);

    // vT[b] = Wv @ q_x[b]^T : per batch M=512, N=4096, K=512
    gemm_nt_mma<<<dim3(NKV/128, DIM/128, BATCH), blk, GEMM_SMEM>>>(
        Wv, q_x, vtb, DIM, NKV, DIM,
        0, (size_t)NKV*DIM, (size_t)DIM*NKV, 1.0f);

    // attn[b] = scale * q[b] @ k[b]^T : M=1024, N=4096, K=512
    gemm_nt_mma<<<dim3(NKV/128, NQ/128, BATCH), blk, GEMM_SMEM>>>(
        qb, kb, attn, NQ, NKV, DIM,
        (size_t)NQ*DIM, (size_t)NKV*DIM, (size_t)NQ*NKV, scale);

    // masked softmax over last axis
    softmax_kernel<<<BATCH*NQ, 256>>>(attn, mask);

    // x[b] = attn[b] @ vT[b]^T : M=1024, N=512, K=4096  (NT, both K-major)
    gemm_nt_mma<<<dim3(DIM/128, NQ/128, BATCH), blk, GEMM_SMEM>>>(
        attn, vtb, xb, NQ, DIM, NKV,
        (size_t)NQ*NKV, (size_t)DIM*NKV, (size_t)NQ*DIM, 1.0f);

    // out = x @ Wproj^T : M=8192, N=512, K=512
    gemm_nt_mma<<<dim3(DIM/128, (BATCH*NQ)/128, 1), blk, GEMM_SMEM>>>(
        xb, Wproj, out, BATCH*NQ, DIM, DIM, 0, 0, 0, 1.0f);
}